// round 11
// baseline (speedup 1.0000x reference)
#include <cuda_runtime.h>
#include <cuda_fp16.h>
#include <cstdint>
#include <math.h>

// Problem constants
#define D_MODEL 1024
#define NHEADS  16
#define DK      64
#define BATCH   2048
#define SEQ     20
#define M_TOTAL (BATCH * SEQ)   // 40960

// ---------------------------------------------------------------------------
// Scratch (fp16): only X and W conversions now — q/k/v never touch gmem.
// ---------------------------------------------------------------------------
__device__ __half g_xh[(size_t)M_TOTAL * D_MODEL];
__device__ __half g_wh[3][(size_t)D_MODEL * D_MODEL];

// ---------------------------------------------------------------------------
// Merged fp32 -> fp16 conversion with streaming 16B loads/stores.
// ---------------------------------------------------------------------------
struct alignas(16) Half8 { __half2 a, b, c, d; };

#define XBLKS 10240
#define WBLKS 256

__global__ __launch_bounds__(256) void f2h_multi(
    const float* __restrict__ X,
    const float* __restrict__ Wq, const float* __restrict__ Wk, const float* __restrict__ Wv)
{
    const float* src;
    __half* dst;
    int local;
    if (blockIdx.x < XBLKS) {
        src = X; dst = g_xh; local = blockIdx.x;
    } else {
        int w = (blockIdx.x - XBLKS) / WBLKS;
        local = (blockIdx.x - XBLKS) % WBLKS;
        src = (w == 0) ? Wq : (w == 1) ? Wk : Wv;
        dst = &g_wh[w][0];
    }
    int c0 = (local * 256 + threadIdx.x) * 2;    // exact fit
    float4 v[4];
    #pragma unroll
    for (int u = 0; u < 4; u++)
        v[u] = __ldcs(&((const float4*)src)[c0 * 2 + u]);
    #pragma unroll
    for (int u = 0; u < 2; u++) {
        Half8 h;
        h.a = __floats2half2_rn(v[2 * u].x,     v[2 * u].y);
        h.b = __floats2half2_rn(v[2 * u].z,     v[2 * u].w);
        h.c = __floats2half2_rn(v[2 * u + 1].x, v[2 * u + 1].y);
        h.d = __floats2half2_rn(v[2 * u + 1].z, v[2 * u + 1].w);
        __stcs((float4*)&((Half8*)dst)[c0 + u], *(float4*)&h);
    }
}

// ---------------------------------------------------------------------------
// MMA / ldmatrix helpers
// ---------------------------------------------------------------------------
__device__ __forceinline__ void mma16(float* c, const uint32_t* a, const uint32_t* b) {
    asm volatile(
        "mma.sync.aligned.m16n8k16.row.col.f32.f16.f16.f32 "
        "{%0,%1,%2,%3}, {%4,%5,%6,%7}, {%8,%9}, {%0,%1,%2,%3};"
        : "+f"(c[0]), "+f"(c[1]), "+f"(c[2]), "+f"(c[3])
        : "r"(a[0]), "r"(a[1]), "r"(a[2]), "r"(a[3]),
          "r"(b[0]), "r"(b[1]));
}
__device__ __forceinline__ void ldmatrix_x4(uint32_t* r, uint32_t addr) {
    asm volatile("ldmatrix.sync.aligned.m8n8.x4.shared.b16 {%0,%1,%2,%3}, [%4];"
                 : "=r"(r[0]), "=r"(r[1]), "=r"(r[2]), "=r"(r[3]) : "r"(addr));
}
__device__ __forceinline__ void ldmatrix_x2(uint32_t* r, uint32_t addr) {
    asm volatile("ldmatrix.sync.aligned.m8n8.x2.shared.b16 {%0,%1}, [%2];"
                 : "=r"(r[0]), "=r"(r[1]) : "r"(addr));
}
__device__ __forceinline__ void ldmatrix_x4_trans(uint32_t* r, uint32_t addr) {
    asm volatile("ldmatrix.sync.aligned.m8n8.x4.trans.shared.b16 {%0,%1,%2,%3}, [%4];"
                 : "=r"(r[0]), "=r"(r[1]), "=r"(r[2]), "=r"(r[3]) : "r"(addr));
}
__device__ __forceinline__ void cp16(uint32_t saddr, const void* g) {
    asm volatile("cp.async.cg.shared.global [%0], [%1], 16;\n" :: "r"(saddr), "l"(g));
}
#define CP_COMMIT() asm volatile("cp.async.commit_group;\n" ::: "memory")
#define CP_WAIT(n)  asm volatile("cp.async.wait_group %0;\n" :: "n"(n) : "memory")

__device__ __forceinline__ uint32_t smem_u32(const void* p) {
    uint32_t a;
    asm("{ .reg .u64 t; cvta.to.shared.u64 t, %1; cvt.u32.u64 %0, t; }"
        : "=r"(a) : "l"(p));
    return a;
}

// ---------------------------------------------------------------------------
// Fused kernel: per CTA, compute q/k/v tiles [160 rows x 128 cols] (8 full
// sequences x 2 heads) with three pipelined GEMM passes into smem, then run
// attention per (seq, head) unit on warps, writing fp32 output directly.
//
// 512 threads = 16 warps. GEMM warp grid 2x8 (warp tile 80x16).
// Pipeline: BK=32, 3 stages, WSTRIDE=20 words/row (conflict-free pattern
// validated in R3/R7: row base multiples of 16 are 0 mod 32 in banks).
// Attention unit per warp: seq = warp/2, head = warp%2 (R9/R10 layouts).
// ---------------------------------------------------------------------------
#define FB_BM 160
#define FB_BN 128
#define FB_BK 32
#define WSTRIDE 20
#define A_STG_WORDS (FB_BM * WSTRIDE)     // 3200
#define B_STG_WORDS (FB_BN * WSTRIDE)     // 2560
#define STG_WORDS   (A_STG_WORDS + B_STG_WORDS)   // 5760
#define NSTAGE 3
#define PIPE_WORDS (NSTAGE * STG_WORDS)   // 17280 (69120 B)
#define TILE_STRIDE 136                    // halves per tile row (272 B = 17x16B)
#define TILE_ROWS 176                      // 160 data + 16 zero pad
#define TILE_HALFS (TILE_ROWS * TILE_STRIDE)       // 23936
#define FB_SMEM_BYTES (PIPE_WORDS * 4 + 3 * TILE_HALFS * 2)  // 69120+143616=212736
#define FB_KT (D_MODEL / FB_BK)            // 32

__global__ __launch_bounds__(512, 1) void fused_proj_attn(
    const float* __restrict__ bq, const float* __restrict__ bk, const float* __restrict__ bv,
    const int* __restrict__ lenbuf, float* __restrict__ out)
{
    extern __shared__ uint32_t smem[];
    const uint32_t sb = smem_u32(smem);

    const int tid  = threadIdx.x;
    const int lane = tid & 31;
    const int warp = tid >> 5;

    const int nBase = blockIdx.x * FB_BN;   // 0..896 (head pair)
    const int mBase = blockIdx.y * FB_BM;   // row base (8 seqs)

    __half* tiles = (__half*)(smem + PIPE_WORDS);   // [3][TILE_ROWS][TILE_STRIDE]

    // Zero the pad rows (160..175) of all three tiles
    {
        uint32_t* padw = (uint32_t*)tiles;
        // pad region per tile: halves [160*136, 176*136) -> words [10880, 11968)
        for (int i = tid; i < 3 * 1088; i += 512) {
            int t = i / 1088, r = i % 1088;
            padw[t * (TILE_HALFS / 2) + 10880 + r] = 0;
        }
    }

    // ---------------- GEMM phase: 3 projections ----------------
    const int wr = warp >> 3;       // 0..1 (80-row halves)
    const int wc = warp & 7;        // 0..7 (16-col slices)
    const int g  = lane >> 2;       // 0..7
    const int tq = lane & 3;        // 0..3

    #pragma unroll 1
    for (int p = 0; p < 3; p++) {
        const __half* Wp = g_wh[p];

        auto load_stage = [&](int stg, int kt) {
            uint32_t base = sb + stg * (STG_WORDS * 4);
            int k0 = kt * FB_BK;
            // A: 160 rows x 4 chunks = 640
            #pragma unroll
            for (int i = 0; i < 2; i++) {
                int e = tid + i * 512;
                if (e < 640) {
                    int r = e >> 2, c = e & 3;
                    cp16(base + (r * WSTRIDE + c * 4) * 4,
                         &g_xh[(size_t)(mBase + r) * D_MODEL + k0 + c * 8]);
                }
            }
            // B: 128 rows x 4 chunks = 512
            {
                int r = tid >> 2, c = tid & 3;
                cp16(base + (A_STG_WORDS + r * WSTRIDE + c * 4) * 4,
                     &Wp[(size_t)(nBase + r) * D_MODEL + k0 + c * 8]);
            }
            CP_COMMIT();
        };

        float c[5][2][4];
        #pragma unroll
        for (int mt = 0; mt < 5; mt++)
            #pragma unroll
            for (int nt = 0; nt < 2; nt++)
                #pragma unroll
                for (int i = 0; i < 4; i++) c[mt][nt][i] = 0.f;

        load_stage(0, 0);
        load_stage(1, 1);

        for (int kt = 0; kt < FB_KT; kt++) {
            int stg = kt % NSTAGE;
            if (kt + 2 < FB_KT) load_stage((kt + 2) % NSTAGE, kt + 2);
            if (kt < FB_KT - 2)      CP_WAIT(2);
            else if (kt == FB_KT - 2) CP_WAIT(1);
            else                      CP_WAIT(0);
            __syncthreads();

            const uint32_t* sAw = smem + stg * STG_WORDS;
            const uint32_t* sBw = sAw + A_STG_WORDS;

            #pragma unroll
            for (int ks = 0; ks < 2; ks++) {
                const int kw = ks * 8 + tq;
                uint32_t af[5][4], bf[2][2];
                #pragma unroll
                for (int mt = 0; mt < 5; mt++) {
                    int rb = (wr * 80 + mt * 16 + g) * WSTRIDE + kw;
                    af[mt][0] = sAw[rb];
                    af[mt][1] = sAw[rb + 8 * WSTRIDE];
                    af[mt][2] = sAw[rb + 4];
                    af[mt][3] = sAw[rb + 8 * WSTRIDE + 4];
                }
                #pragma unroll
                for (int nt = 0; nt < 2; nt++) {
                    int rb = (wc * 16 + nt * 8 + g) * WSTRIDE + kw;
                    bf[nt][0] = sBw[rb];
                    bf[nt][1] = sBw[rb + 4];
                }
                #pragma unroll
                for (int mt = 0; mt < 5; mt++)
                    #pragma unroll
                    for (int nt = 0; nt < 2; nt++)
                        mma16(c[mt][nt], af[mt], bf[nt]);
            }
            __syncthreads();
        }

        // Epilogue: bias add, fp16 store into tile p
        const float* bp = (p == 0) ? bq : (p == 1) ? bk : bv;
        __half* tp = tiles + p * TILE_HALFS;
        #pragma unroll
        for (int mt = 0; mt < 5; mt++) {
            #pragma unroll
            for (int nt = 0; nt < 2; nt++) {
                int row = wr * 80 + mt * 16 + g;
                int col = wc * 16 + nt * 8 + 2 * tq;
                float b0 = bp[nBase + col], b1 = bp[nBase + col + 1];
                __half2 h01 = __floats2half2_rn(c[mt][nt][0] + b0, c[mt][nt][1] + b1);
                __half2 h23 = __floats2half2_rn(c[mt][nt][2] + b0, c[mt][nt][3] + b1);
                *(__half2*)&tp[row * TILE_STRIDE + col]       = h01;
                *(__half2*)&tp[(row + 8) * TILE_STRIDE + col] = h23;
            }
        }
    }
    __syncthreads();

    // ---------------- Attention phase: 1 unit per warp ----------------
    {
        const int seq  = warp >> 1;          // 0..7
        const int head = warp & 1;           // 0..1
        const int b    = blockIdx.y * 8 + seq;
        const int ch   = head * DK;          // local col base

        const uint32_t qb = smem_u32(tiles + 0 * TILE_HALFS);
        const uint32_t kb = smem_u32(tiles + 1 * TILE_HALFS);
        const uint32_t vb = smem_u32(tiles + 2 * TILE_HALFS);
        const int rb = seq * SEQ;            // row base in tile

        bool is64 = (lenbuf[1] == 0);
        int len = is64 ? lenbuf[2 * b] : lenbuf[b];

        // --- Score: S = q @ k^T, M=32 (20 valid), N=24 (20 valid), K=64 ---
        float sc[2][3][4];
        #pragma unroll
        for (int mt = 0; mt < 2; mt++)
            #pragma unroll
            for (int nt = 0; nt < 3; nt++)
                #pragma unroll
                for (int i = 0; i < 4; i++) sc[mt][nt][i] = 0.f;

        #pragma unroll
        for (int ks = 0; ks < 4; ks++) {
            uint32_t bfrag[3][2];
            #pragma unroll
            for (int nt = 0; nt < 3; nt++) {
                int l = lane & 15;
                int row = rb + nt * 8 + (l & 7);
                int col = ch + ks * 16 + ((l >> 3) & 1) * 8;
                ldmatrix_x2(bfrag[nt], kb + (row * TILE_STRIDE + col) * 2);
            }
            #pragma unroll
            for (int mt = 0; mt < 2; mt++) {
                uint32_t afrag[4];
                int row = rb + mt * 16 + (lane & 15);
                int col = ch + ks * 16 + (lane >> 4) * 8;
                ldmatrix_x4(afrag, qb + (row * TILE_STRIDE + col) * 2);
                #pragma unroll
                for (int nt = 0; nt < 3; nt++)
                    mma16(sc[mt][nt], afrag, bfrag[nt]);
            }
        }

        // --- exp + key mask, row sums (shfl over lane%4), normalize ---
        #pragma unroll
        for (int mt = 0; mt < 2; mt++)
            #pragma unroll
            for (int nt = 0; nt < 3; nt++)
                #pragma unroll
                for (int idx = 0; idx < 4; idx++) {
                    int j = nt * 8 + 2 * (lane & 3) + (idx & 1);
                    float e = (j < len) ? __expf(sc[mt][nt][idx] * 0.125f) : 0.f;
                    sc[mt][nt][idx] = e;
                }
        float inv[2][2];
        #pragma unroll
        for (int mt = 0; mt < 2; mt++)
            #pragma unroll
            for (int hr = 0; hr < 2; hr++) {
                float s = 0.f;
                #pragma unroll
                for (int nt = 0; nt < 3; nt++)
                    s += sc[mt][nt][2 * hr] + sc[mt][nt][2 * hr + 1];
                s += __shfl_xor_sync(0xffffffffu, s, 1);
                s += __shfl_xor_sync(0xffffffffu, s, 2);
                inv[mt][hr] = 1.f / (s + 1e-8f);
            }

        // --- Build P fp16 A-fragments (C-frag layout == A-frag layout) ---
        // Pp[ks][mt][4]: ks chunk covers k=16ks..16ks+15; k>=24 zero.
        uint32_t Pp[2][2][4];
        #pragma unroll
        for (int mt = 0; mt < 2; mt++) {
            #pragma unroll
            for (int ks = 0; ks < 2; ks++) {
                #pragma unroll
                for (int half8 = 0; half8 < 2; half8++) {   // k sub-octet
                    int nt = ks * 2 + half8;
                    #pragma unroll
                    for (int hr = 0; hr < 2; hr++) {
                        uint32_t v;
                        if (nt < 3) {
                            __half2 h = __floats2half2_rn(
                                sc[mt][nt][2 * hr]     * inv[mt][hr],
                                sc[mt][nt][2 * hr + 1] * inv[mt][hr]);
                            v = *(uint32_t*)&h;
                        } else v = 0;
                        // frag index: [0]=(r,k0) [1]=(r+8,k0) [2]=(r,k0+8) [3]=(r+8,k0+8)
                        Pp[ks][mt][half8 * 2 + hr] = v;
                    }
                }
            }
        }

        // --- Md fp16 A-fragments: Md[r][j] = -(|r-j|), j<20 else 0 ---
        uint32_t Mf[2][2][4];
        #pragma unroll
        for (int ks = 0; ks < 2; ks++)
            #pragma unroll
            for (int mt = 0; mt < 2; mt++)
                #pragma unroll
                for (int idx = 0; idx < 4; idx++) {
                    int r = mt * 16 + (lane >> 2) + (idx & 1) * 8;   // idx 1,3 -> r+8
                    int j0 = ks * 16 + 2 * (lane & 3) + (idx >> 1) * 8;
                    float v0 = (j0     < SEQ) ? -fabsf((float)(r - j0))       : 0.f;
                    float v1 = (j0 + 1 < SEQ) ? -fabsf((float)(r - (j0 + 1))) : 0.f;
                    __half2 h = __floats2half2_rn(v0, v1);
                    Mf[ks][mt][idx] = *(uint32_t*)&h;
                }

        // --- Output: out = P @ v + Md @ v, M=32, N=64, K=32 ---
        float co[2][8][4];
        #pragma unroll
        for (int mt = 0; mt < 2; mt++)
            #pragma unroll
            for (int nt = 0; nt < 8; nt++)
                #pragma unroll
                for (int i = 0; i < 4; i++) co[mt][nt][i] = 0.f;

        #pragma unroll
        for (int grp = 0; grp < 4; grp++) {
            #pragma unroll
            for (int ks = 0; ks < 2; ks++) {
                uint32_t bfr[4];
                int row = rb + ks * 16 + (lane & 15);
                int col = ch + grp * 16 + (lane >> 4) * 8;
                ldmatrix_x4_trans(bfr, vb + (row * TILE_STRIDE + col) * 2);
                #pragma unroll
                for (int mt = 0; mt < 2; mt++) {
                    mma16(co[mt][2 * grp],     Pp[ks][mt], bfr);
                    mma16(co[mt][2 * grp + 1], Pp[ks][mt], bfr + 2);
                    mma16(co[mt][2 * grp],     Mf[ks][mt], bfr);
                    mma16(co[mt][2 * grp + 1], Mf[ks][mt], bfr + 2);
                }
            }
        }

        // --- Store fp32 out ---
        #pragma unroll
        for (int mt = 0; mt < 2; mt++) {
            #pragma unroll
            for (int hr = 0; hr < 2; hr++) {
                int r = mt * 16 + (lane >> 2) + hr * 8;
                if (r < SEQ) {
                    size_t rowb = (size_t)(b * SEQ + r) * D_MODEL
                                + nBase + ch + 2 * (lane & 3);
                    #pragma unroll
                    for (int nt = 0; nt < 8; nt++) {
                        float2 o = make_float2(co[mt][nt][2 * hr], co[mt][nt][2 * hr + 1]);
                        *(float2*)&out[rowb + nt * 8] = o;
                    }
                }
            }
        }
    }
}

// ---------------------------------------------------------------------------
// Inputs (metadata order): Q, W_Q, b_Q, W_K, b_K, W_V, b_V, length
// ---------------------------------------------------------------------------
extern "C" void kernel_launch(void* const* d_in, const int* in_sizes, int n_in,
                              void* d_out, int out_size)
{
    const float* X  = (const float*)d_in[0];
    const float* Wq = (const float*)d_in[1];
    const float* bq = (const float*)d_in[2];
    const float* Wk = (const float*)d_in[3];
    const float* bk = (const float*)d_in[4];
    const float* Wv = (const float*)d_in[5];
    const float* bv = (const float*)d_in[6];
    const int*   ln = (const int*)d_in[7];

    f2h_multi<<<XBLKS + 3 * WBLKS, 256>>>(X, Wq, Wk, Wv);

    cudaFuncSetAttribute(fused_proj_attn,
                         cudaFuncAttributeMaxDynamicSharedMemorySize, FB_SMEM_BYTES);

    // grid.x = head-pair tiles (8), grid.y = 8-sequence row tiles (256)
    dim3 grid(D_MODEL / FB_BN, M_TOTAL / FB_BM);
    fused_proj_attn<<<grid, 512, FB_SMEM_BYTES>>>(bq, bk, bv, ln, (float*)d_out);
}

// round 12
// speedup vs baseline: 1.1554x; 1.1554x over previous
#include <cuda_runtime.h>
#include <cuda_fp16.h>
#include <cstdint>
#include <math.h>

// Problem constants
#define D_MODEL 1024
#define NHEADS  16
#define DK      64
#define BATCH   2048
#define SEQ     20
#define M_TOTAL (BATCH * SEQ)   // 40960

// ---------------------------------------------------------------------------
// Scratch (fp16)
// ---------------------------------------------------------------------------
__device__ __half g_xh[(size_t)M_TOTAL * D_MODEL];
__device__ __half g_wh[3][(size_t)D_MODEL * D_MODEL];
__device__ __half g_qh[(size_t)M_TOTAL * D_MODEL];
__device__ __half g_kh[(size_t)M_TOTAL * D_MODEL];
__device__ __half g_vh[(size_t)M_TOTAL * D_MODEL];

// ---------------------------------------------------------------------------
// Merged fp32 -> fp16 conversion with streaming 16B loads/stores.
// ---------------------------------------------------------------------------
struct alignas(16) Half8 { __half2 a, b, c, d; };

#define XBLKS 10240
#define WBLKS 256

__global__ __launch_bounds__(256) void f2h_multi(
    const float* __restrict__ X,
    const float* __restrict__ Wq, const float* __restrict__ Wk, const float* __restrict__ Wv)
{
    const float* src;
    __half* dst;
    int local;
    if (blockIdx.x < XBLKS) {
        src = X; dst = g_xh; local = blockIdx.x;
    } else {
        int w = (blockIdx.x - XBLKS) / WBLKS;
        local = (blockIdx.x - XBLKS) % WBLKS;
        src = (w == 0) ? Wq : (w == 1) ? Wk : Wv;
        dst = &g_wh[w][0];
    }
    int c0 = (local * 256 + threadIdx.x) * 2;    // exact fit
    float4 v[4];
    #pragma unroll
    for (int u = 0; u < 4; u++)
        v[u] = __ldcs(&((const float4*)src)[c0 * 2 + u]);
    #pragma unroll
    for (int u = 0; u < 2; u++) {
        Half8 h;
        h.a = __floats2half2_rn(v[2 * u].x,     v[2 * u].y);
        h.b = __floats2half2_rn(v[2 * u].z,     v[2 * u].w);
        h.c = __floats2half2_rn(v[2 * u + 1].x, v[2 * u + 1].y);
        h.d = __floats2half2_rn(v[2 * u + 1].z, v[2 * u + 1].w);
        __stcs((float4*)&((Half8*)dst)[c0 + u], *(float4*)&h);
    }
}

// ---------------------------------------------------------------------------
// MMA / ldmatrix helpers
// ---------------------------------------------------------------------------
__device__ __forceinline__ void mma16(float* c, const uint32_t* a, const uint32_t* b) {
    asm volatile(
        "mma.sync.aligned.m16n8k16.row.col.f32.f16.f16.f32 "
        "{%0,%1,%2,%3}, {%4,%5,%6,%7}, {%8,%9}, {%0,%1,%2,%3};"
        : "+f"(c[0]), "+f"(c[1]), "+f"(c[2]), "+f"(c[3])
        : "r"(a[0]), "r"(a[1]), "r"(a[2]), "r"(a[3]),
          "r"(b[0]), "r"(b[1]));
}

__device__ __forceinline__ void ldmatrix_x4(uint32_t* r, uint32_t addr) {
    asm volatile("ldmatrix.sync.aligned.m8n8.x4.shared.b16 {%0,%1,%2,%3}, [%4];"
                 : "=r"(r[0]), "=r"(r[1]), "=r"(r[2]), "=r"(r[3]) : "r"(addr));
}
__device__ __forceinline__ void ldmatrix_x2(uint32_t* r, uint32_t addr) {
    asm volatile("ldmatrix.sync.aligned.m8n8.x2.shared.b16 {%0,%1}, [%2];"
                 : "=r"(r[0]), "=r"(r[1]) : "r"(addr));
}

__device__ __forceinline__ void cp16(uint32_t saddr, const void* g) {
    asm volatile("cp.async.cg.shared.global [%0], [%1], 16;\n" :: "r"(saddr), "l"(g));
}
#define CP_COMMIT() asm volatile("cp.async.commit_group;\n" ::: "memory")
#define CP_WAIT(n)  asm volatile("cp.async.wait_group %0;\n" :: "n"(n) : "memory")

__device__ __forceinline__ uint32_t smem_u32(const void* p) {
    uint32_t a;
    asm("{ .reg .u64 t; cvta.to.shared.u64 t, %1; cvt.u32.u64 %0, t; }"
        : "=r"(a) : "l"(p));
    return a;
}

// ---------------------------------------------------------------------------
// Projection GEMM (exact R7 config — best measured): Y = X @ W^T + b.
// BM=128, BN=128, BK=32, 3-stage cp.async, 2 CTAs/SM.
// ---------------------------------------------------------------------------
#define GM_BM 128
#define GM_BN 128
#define GM_BK 32
#define WSTRIDE 20
#define A_STG_WORDS (GM_BM * WSTRIDE)     // 2560
#define B_STG_WORDS (GM_BN * WSTRIDE)     // 2560
#define STG_WORDS   (A_STG_WORDS + B_STG_WORDS)  // 5120
#define NSTAGE 3
#define GM_SMEM_BYTES (NSTAGE * STG_WORDS * 4)   // 61440
#define GM_KT (D_MODEL / GM_BK)           // 32

__global__ __launch_bounds__(256, 2) void proj_gemm(
    const float* __restrict__ bq, const float* __restrict__ bk, const float* __restrict__ bv)
{
    extern __shared__ uint32_t smem[];
    const uint32_t sb = smem_u32(smem);

    const int tid  = threadIdx.x;
    const int lane = tid & 31;
    const int warp = tid >> 5;
    const int wr   = warp >> 2;
    const int wc   = warp & 3;
    const int g    = lane >> 2;
    const int tq   = lane & 3;

    const int proj  = blockIdx.x >> 3;
    const int nBase = (blockIdx.x & 7) * GM_BN;
    const int mBase = blockIdx.y * GM_BM;

    const __half* Wp = g_wh[proj];

    auto load_stage = [&](int stg, int kt) {
        uint32_t base = sb + stg * (STG_WORDS * 4);
        int k0 = kt * GM_BK;
        #pragma unroll
        for (int i = 0; i < 2; i++) {
            int ch = tid + i * 256;
            int r = ch >> 2, c = ch & 3;
            cp16(base + (r * WSTRIDE + c * 4) * 4,
                 &g_xh[(size_t)(mBase + r) * D_MODEL + k0 + c * 8]);
        }
        #pragma unroll
        for (int i = 0; i < 2; i++) {
            int ch = tid + i * 256;
            int r = ch >> 2, c = ch & 3;
            cp16(base + (A_STG_WORDS + r * WSTRIDE + c * 4) * 4,
                 &Wp[(size_t)(nBase + r) * D_MODEL + k0 + c * 8]);
        }
        CP_COMMIT();
    };

    float c[4][4][4];
    #pragma unroll
    for (int mt = 0; mt < 4; mt++)
        #pragma unroll
        for (int nt = 0; nt < 4; nt++)
            #pragma unroll
            for (int i = 0; i < 4; i++) c[mt][nt][i] = 0.f;

    load_stage(0, 0);
    load_stage(1, 1);

    for (int kt = 0; kt < GM_KT; kt++) {
        int stg = kt % NSTAGE;
        if (kt + 2 < GM_KT) load_stage((kt + 2) % NSTAGE, kt + 2);
        if (kt < GM_KT - 2)      CP_WAIT(2);
        else if (kt == GM_KT - 2) CP_WAIT(1);
        else                      CP_WAIT(0);
        __syncthreads();

        const uint32_t* sAw = smem + stg * STG_WORDS;
        const uint32_t* sBw = sAw + A_STG_WORDS;

        #pragma unroll
        for (int ks = 0; ks < 2; ks++) {
            const int kw = ks * 8 + tq;
            uint32_t af[4][4], bf[4][2];
            #pragma unroll
            for (int mt = 0; mt < 4; mt++) {
                int rb = (wr * 64 + mt * 16 + g) * WSTRIDE + kw;
                af[mt][0] = sAw[rb];
                af[mt][1] = sAw[rb + 8 * WSTRIDE];
                af[mt][2] = sAw[rb + 4];
                af[mt][3] = sAw[rb + 8 * WSTRIDE + 4];
            }
            #pragma unroll
            for (int nt = 0; nt < 4; nt++) {
                int rb = (wc * 32 + nt * 8 + g) * WSTRIDE + kw;
                bf[nt][0] = sBw[rb];
                bf[nt][1] = sBw[rb + 4];
            }
            #pragma unroll
            for (int mt = 0; mt < 4; mt++)
                #pragma unroll
                for (int nt = 0; nt < 4; nt++)
                    mma16(c[mt][nt], af[mt], bf[nt]);
        }
        __syncthreads();
    }

    const float* bp = (proj == 0) ? bq : (proj == 1) ? bk : bv;
    __half* outp    = (proj == 0) ? g_qh : (proj == 1) ? g_kh : g_vh;
    #pragma unroll
    for (int mt = 0; mt < 4; mt++) {
        #pragma unroll
        for (int nt = 0; nt < 4; nt++) {
            int row = mBase + wr * 64 + mt * 16 + g;
            int col = nBase + wc * 32 + nt * 8 + 2 * tq;
            float b0 = bp[col], b1 = bp[col + 1];
            __half2 h01 = __floats2half2_rn(c[mt][nt][0] + b0, c[mt][nt][1] + b1);
            __half2 h23 = __floats2half2_rn(c[mt][nt][2] + b0, c[mt][nt][3] + b1);
            *(__half2*)&outp[(size_t)row * D_MODEL + col] = h01;
            *(__half2*)&outp[(size_t)(row + 8) * D_MODEL + col] = h23;
        }
    }
}

// ---------------------------------------------------------------------------
// Attention + decay (R9-validated). Score phase on tensor cores.
// Block order REVERSED so the most recently written q/k/v (still L2-warm
// from the GEMM's final waves) is consumed first. Output uses streaming
// stores so the 320 MB write-once stream doesn't evict q/k/v from L2.
// ---------------------------------------------------------------------------
#define QK_STRIDE 72   // halves per row; 144 B = 9 x 16 B (ldmatrix-aligned)

__global__ __launch_bounds__(128) void attn_kernel(
    const int* __restrict__ lenbuf, float* __restrict__ out)
{
    const int bh = (BATCH * NHEADS - 1) - blockIdx.x;   // reversed order
    const int b  = bh >> 4;
    const int h  = bh & 15;
    const int tid  = threadIdx.x;
    const int warp = tid >> 5;
    const int lane = tid & 31;

    __shared__ __align__(16) __half sqh[32][QK_STRIDE];
    __shared__ __align__(16) __half skh[24][QK_STRIDE];
    __shared__ __align__(16) float sv[SEQ][68];
    __shared__ float ssc[SEQ][24];
    __shared__ float sinv[SEQ];
    __shared__ __align__(16) float wgtT[SEQ][24];   // [j][i]

    // Zero-fill q/k smem (padded rows must be 0 so MMA garbage is benign)
    for (int i = tid; i < 32 * (QK_STRIDE / 2); i += 128) ((uint32_t*)sqh)[i] = 0;
    for (int i = tid; i < 24 * (QK_STRIDE / 2); i += 128) ((uint32_t*)skh)[i] = 0;
    __syncthreads();

    // Load q/k fp16 straight through; v converted to fp32
    {
        size_t base = (size_t)(b * SEQ) * D_MODEL + h * DK;
        for (int e = tid; e < SEQ * (DK / 8); e += 128) {
            int s = e >> 3, d8 = (e & 7) * 8;
            size_t gi = base + (size_t)s * D_MODEL + d8;
            Half8 q8 = *(const Half8*)&g_qh[gi];
            Half8 k8 = *(const Half8*)&g_kh[gi];
            Half8 v8 = *(const Half8*)&g_vh[gi];
            *(Half8*)&sqh[s][d8] = q8;
            *(Half8*)&skh[s][d8] = k8;
            float2 fa = __half22float2(v8.a), fb = __half22float2(v8.b);
            float2 fc = __half22float2(v8.c), fd = __half22float2(v8.d);
            float4 v0 = make_float4(fa.x, fa.y, fb.x, fb.y);
            float4 v1 = make_float4(fc.x, fc.y, fd.x, fd.y);
            *(float4*)&sv[s][d8]     = v0;
            *(float4*)&sv[s][d8 + 4] = v1;
        }
    }
    __syncthreads();

    // length may be int64 or int32 (jax x64 config). All lengths >= 1,
    // so int32-view word 1 == 0 iff buffer is int64.
    bool is64 = (lenbuf[1] == 0);
    int len = is64 ? lenbuf[2 * b] : lenbuf[b];

    // Score phase: warps 0-2, each computes cols [8w, 8w+8) for all 32 rows.
    if (warp < 3) {
        float c[2][4];
        #pragma unroll
        for (int mt = 0; mt < 2; mt++)
            #pragma unroll
            for (int i = 0; i < 4; i++) c[mt][i] = 0.f;

        const uint32_t sq_base = smem_u32(&sqh[0][0]);
        const uint32_t sk_base = smem_u32(&skh[0][0]);

        #pragma unroll
        for (int ks = 0; ks < 4; ks++) {
            uint32_t bfrag[2];
            {
                int l = lane & 15;
                int row = warp * 8 + (l & 7);
                int col = ks * 16 + ((l >> 3) & 1) * 8;
                ldmatrix_x2(bfrag, sk_base + (row * QK_STRIDE + col) * 2);
            }
            #pragma unroll
            for (int mt = 0; mt < 2; mt++) {
                uint32_t afrag[4];
                int row = mt * 16 + (lane & 15);
                int col = ks * 16 + (lane >> 4) * 8;
                ldmatrix_x4(afrag, sq_base + (row * QK_STRIDE + col) * 2);
                mma16(c[mt], afrag, bfrag);
            }
        }

        int jc = warp * 8 + 2 * (lane & 3);
        bool jv0 = (jc < SEQ), jv1 = (jc + 1 < SEQ);
        float m0 = (jc < len) ? 1.f : 0.f;
        float m1 = (jc + 1 < len) ? 1.f : 0.f;
        #pragma unroll
        for (int mt = 0; mt < 2; mt++) {
            #pragma unroll
            for (int hrow = 0; hrow < 2; hrow++) {
                int r = mt * 16 + (lane >> 2) + hrow * 8;
                if (r < SEQ) {
                    if (jv0) ssc[r][jc]     = m0 * __expf(c[mt][2 * hrow]     * 0.125f);
                    if (jv1) ssc[r][jc + 1] = m1 * __expf(c[mt][2 * hrow + 1] * 0.125f);
                }
            }
        }
    }
    __syncthreads();

    if (tid < SEQ) {
        float s = 0.f;
        #pragma unroll
        for (int j = 0; j < SEQ; j++) s += ssc[tid][j];
        sinv[tid] = 1.f / (s + 1e-8f);
    }
    __syncthreads();

    for (int e = tid; e < SEQ * SEQ; e += 128) {
        int i = e % SEQ, j = e / SEQ;
        wgtT[j][i] = ssc[i][j] * sinv[i] - (float)((i > j) ? (i - j) : (j - i));
    }
    __syncthreads();

    // Output: 4 rows x 4 cols per thread on threads 0..79, streaming stores
    if (tid < 80) {
        int i0 = (tid / 16) * 4;
        int d0 = (tid & 15) * 4;
        float4 o0 = {0, 0, 0, 0}, o1 = {0, 0, 0, 0}, o2 = {0, 0, 0, 0}, o3 = {0, 0, 0, 0};
        #pragma unroll
        for (int j = 0; j < SEQ; j++) {
            float4 vv = *(const float4*)&sv[j][d0];
            float4 w  = *(const float4*)&wgtT[j][i0];
            o0.x += w.x * vv.x; o0.y += w.x * vv.y; o0.z += w.x * vv.z; o0.w += w.x * vv.w;
            o1.x += w.y * vv.x; o1.y += w.y * vv.y; o1.z += w.y * vv.z; o1.w += w.y * vv.w;
            o2.x += w.z * vv.x; o2.y += w.z * vv.y; o2.z += w.z * vv.z; o2.w += w.z * vv.w;
            o3.x += w.w * vv.x; o3.y += w.w * vv.y; o3.z += w.w * vv.z; o3.w += w.w * vv.w;
        }
        size_t base = (size_t)(b * SEQ + i0) * D_MODEL + h * DK + d0;
        __stcs((float4*)&out[base],               o0);
        __stcs((float4*)&out[base + D_MODEL],     o1);
        __stcs((float4*)&out[base + 2 * D_MODEL], o2);
        __stcs((float4*)&out[base + 3 * D_MODEL], o3);
    }
}

// ---------------------------------------------------------------------------
// Inputs (metadata order): Q, W_Q, b_Q, W_K, b_K, W_V, b_V, length
// ---------------------------------------------------------------------------
extern "C" void kernel_launch(void* const* d_in, const int* in_sizes, int n_in,
                              void* d_out, int out_size)
{
    const float* X  = (const float*)d_in[0];
    const float* Wq = (const float*)d_in[1];
    const float* bq = (const float*)d_in[2];
    const float* Wk = (const float*)d_in[3];
    const float* bk = (const float*)d_in[4];
    const float* Wv = (const float*)d_in[5];
    const float* bv = (const float*)d_in[6];
    const int*   ln = (const int*)d_in[7];

    f2h_multi<<<XBLKS + 3 * WBLKS, 256>>>(X, Wq, Wk, Wv);

    cudaFuncSetAttribute(proj_gemm,
                         cudaFuncAttributeMaxDynamicSharedMemorySize, GM_SMEM_BYTES);

    dim3 grid(3 * (D_MODEL / GM_BN), M_TOTAL / GM_BM);   // (24, 320)
    proj_gemm<<<grid, 256, GM_SMEM_BYTES>>>(bq, bk, bv);

    attn_kernel<<<BATCH * NHEADS, 128>>>(ln, (float*)d_out);
}